// round 3
// baseline (speedup 1.0000x reference)
#include <cuda_runtime.h>
#include <cstdint>
#include <math.h>

typedef unsigned long long ull;

// Problem constants
#define Bn 2048
#define Sn 50
#define En 256
#define Hn 512
#define Gn 2048        // 4*H
#define Wn 256
#define Ln 50
#define ND (Gn + Wn)   // 2304 : [interleaved dec gates | W2 rows]
#define Vn 51
#define BK 16

// ---------------- device scratch (no allocations allowed) ----------------
__device__ float g_h0[Bn * Hn];
__device__ float g_h1[Bn * Hn];
__device__ float g_c[Bn * Hn];
__device__ float g_enc[(size_t)Bn * Sn * Hn];     // encoder hidden states [B,S,H]
__device__ float g_blend1[(size_t)Bn * Sn * Wn];  // [B,S,W]
__device__ float g_blend2[Bn * Wn];
__device__ unsigned char g_mask[Bn * Sn];
__device__ float g_encW2[Gn * Hn];                // interleaved [4j+g, k] of enc_Whh
__device__ float g_decW2[ND * Hn];                // interleaved dec_Whh rows then W2 rows
__device__ float g_bias_dec2[Gn];                 // interleaved decoder bias
__device__ float g_P[Vn * Gn];                    // emb@Wih^T + enc bias, interleaved cols

// ---------------- f32x2 helpers ----------------
__device__ __forceinline__ ull pk(float x, float y) {
    ull r; asm("mov.b64 %0,{%1,%2};" : "=l"(r) : "f"(x), "f"(y)); return r;
}
__device__ __forceinline__ void fma2(ull& d, ull a, ull b) {
    asm("fma.rn.f32x2 %0,%1,%2,%3;" : "=l"(d) : "l"(a), "l"(b), "l"(d));
}
__device__ __forceinline__ float2 up(ull v) {
    float2 f; asm("mov.b64 {%0,%1},%2;" : "=f"(f.x), "=f"(f.y) : "l"(v)); return f;
}

__device__ __forceinline__ float sigf(float x) { return 1.0f / (1.0f + expf(-x)); }

// ---------------- prep: weight reorder + interleave ----------------
__global__ void k_prep(const float* __restrict__ eWhh,
                       const float* __restrict__ dWhh, const float* __restrict__ dbih,
                       const float* __restrict__ dbhh, const float* __restrict__ W2) {
    int idx = blockIdx.x * blockDim.x + threadIdx.x;
    if (idx < Gn * Hn) {
        int n2 = idx / Hn, k = idx % Hn;
        int g = n2 & 3, j = n2 >> 2;
        g_encW2[idx] = eWhh[(g * Hn + j) * Hn + k];
    }
    if (idx < ND * Hn) {
        int n2 = idx / Hn, k = idx % Hn;
        if (n2 < Gn) {
            int g = n2 & 3, j = n2 >> 2;
            g_decW2[idx] = dWhh[(g * Hn + j) * Hn + k];
        } else {
            g_decW2[idx] = W2[(size_t)(n2 - Gn) * Hn + k];
        }
    }
    if (idx < Gn) {
        int g = idx & 3, j = idx >> 2;
        int r = g * Hn + j;
        g_bias_dec2[idx] = dbih[r] + dbhh[r];
    }
}

// P[v][n2] = emb[v] . Wih[r] + bih[r] + bhh[r],  r = (n2&3)*H + (n2>>2)
__global__ void k_prep_P(const float* __restrict__ emb, const float* __restrict__ eWih,
                         const float* __restrict__ ebih, const float* __restrict__ ebhh) {
    int idx = blockIdx.x * blockDim.x + threadIdx.x;
    if (idx >= Vn * Gn) return;
    int v = idx / Gn, n2 = idx % Gn;
    int g = n2 & 3, j = n2 >> 2;
    int r = g * Hn + j;
    const float4* e = reinterpret_cast<const float4*>(emb + (size_t)v * En);
    const float4* w = reinterpret_cast<const float4*>(eWih + (size_t)r * En);
    float s = 0.0f;
    #pragma unroll 8
    for (int k = 0; k < En / 4; k++) {
        float4 a = __ldg(e + k), b = __ldg(w + k);
        s += a.x * b.x + a.y * b.y + a.z * b.z + a.w * b.w;
    }
    g_P[idx] = s + ebih[r] + ebhh[r];
}

__global__ void k_init() {
    int idx = blockIdx.x * blockDim.x + threadIdx.x;
    if (idx < Bn * Hn) { g_h0[idx] = 0.0f; g_c[idx] = 0.0f; }
    if (idx < Bn * Sn) g_mask[idx] = 0;
}

// decoder first cell: h_prev = 0 -> gates = bias only; c0 = enc last hidden
__global__ void k_dec0() {
    int idx = blockIdx.x * blockDim.x + threadIdx.x;
    if (idx >= Bn * Hn) return;
    int b = idx / Hn, j = idx % Hn;
    float gi = g_bias_dec2[4 * j + 0], gf = g_bias_dec2[4 * j + 1];
    float gg = g_bias_dec2[4 * j + 2], go = g_bias_dec2[4 * j + 3];
    float c0 = g_enc[((size_t)b * Sn + (Sn - 1)) * Hn + j];
    float cn = sigf(gf) * c0 + sigf(gi) * tanhf(gg);
    g_c[idx] = cn;
    g_h0[idx] = sigf(go) * tanhf(cn);
}

// ---------------- fused GEMM (FFMA2, BK=16, dup-A smem, double-buffered) ----
// C[M,N] = A[M,512] * Bw[N,512]^T ; epilogue per MODE:
//   MODE 0: plain store to Cout (ldc)
//   MODE 1: encoder: add P[token], LSTM cell -> hout, cst, enc[:,t,:]
//   MODE 2: decoder: bn<Gn -> add bias2 + cell -> hout,cst ; bn>=Gn -> store blend2
template <int MODE>
__global__ __launch_bounds__(256, 2) void gemm_fused(
    const float* __restrict__ A,
    const float* __restrict__ Bw,
    const float* __restrict__ bias2,
    const float* __restrict__ P,
    const int* __restrict__ tok,
    float* __restrict__ Cout, int ldc,
    float* __restrict__ hout,
    float* __restrict__ cst,
    float* __restrict__ enc, int t) {
    __shared__ ull   As[2][BK][128];   // duplicated lanes: both halves == A value
    __shared__ float Bs[2][BK][128];
    const int tid = threadIdx.x;
    const int bm = blockIdx.y * 128, bn = blockIdx.x * 128;
    const int lr = tid >> 1;           // 0..127 : tile row
    const int lc = (tid & 1) << 3;     // 0 or 8 : k offset
    const int tx = tid & 15, ty = tid >> 4;
    const float* Aa = A + (size_t)(bm + lr) * Hn + lc;
    const float* Bb = Bw + (size_t)(bn + lr) * Hn + lc;

    ull acc[8][4];
#pragma unroll
    for (int i = 0; i < 8; i++)
#pragma unroll
        for (int p = 0; p < 4; p++) acc[i][p] = 0ull;

    float4 av0 = *reinterpret_cast<const float4*>(Aa);
    float4 av1 = *reinterpret_cast<const float4*>(Aa + 4);
    float4 bv0 = *reinterpret_cast<const float4*>(Bb);
    float4 bv1 = *reinterpret_cast<const float4*>(Bb + 4);
    {
        As[0][lc + 0][lr] = pk(av0.x, av0.x); As[0][lc + 1][lr] = pk(av0.y, av0.y);
        As[0][lc + 2][lr] = pk(av0.z, av0.z); As[0][lc + 3][lr] = pk(av0.w, av0.w);
        As[0][lc + 4][lr] = pk(av1.x, av1.x); As[0][lc + 5][lr] = pk(av1.y, av1.y);
        As[0][lc + 6][lr] = pk(av1.z, av1.z); As[0][lc + 7][lr] = pk(av1.w, av1.w);
        Bs[0][lc + 0][lr] = bv0.x; Bs[0][lc + 1][lr] = bv0.y;
        Bs[0][lc + 2][lr] = bv0.z; Bs[0][lc + 3][lr] = bv0.w;
        Bs[0][lc + 4][lr] = bv1.x; Bs[0][lc + 5][lr] = bv1.y;
        Bs[0][lc + 6][lr] = bv1.z; Bs[0][lc + 7][lr] = bv1.w;
    }
    __syncthreads();

#pragma unroll 1
    for (int kt = 0; kt < Hn / BK; kt++) {
        const int cur = kt & 1;
        if (kt < Hn / BK - 1) {
            av0 = *reinterpret_cast<const float4*>(Aa + (kt + 1) * BK);
            av1 = *reinterpret_cast<const float4*>(Aa + (kt + 1) * BK + 4);
            bv0 = *reinterpret_cast<const float4*>(Bb + (kt + 1) * BK);
            bv1 = *reinterpret_cast<const float4*>(Bb + (kt + 1) * BK + 4);
        }
#pragma unroll
        for (int kk = 0; kk < BK; kk++) {
            ulonglong2 a01 = *reinterpret_cast<const ulonglong2*>(&As[cur][kk][ty * 4]);
            ulonglong2 a23 = *reinterpret_cast<const ulonglong2*>(&As[cur][kk][ty * 4 + 2]);
            ulonglong2 a45 = *reinterpret_cast<const ulonglong2*>(&As[cur][kk][64 + ty * 4]);
            ulonglong2 a67 = *reinterpret_cast<const ulonglong2*>(&As[cur][kk][64 + ty * 4 + 2]);
            ulonglong2 b01 = *reinterpret_cast<const ulonglong2*>(&Bs[cur][kk][tx * 4]);
            ulonglong2 b23 = *reinterpret_cast<const ulonglong2*>(&Bs[cur][kk][64 + tx * 4]);
            ull a[8] = {a01.x, a01.y, a23.x, a23.y, a45.x, a45.y, a67.x, a67.y};
            ull b[4] = {b01.x, b01.y, b23.x, b23.y};
#pragma unroll
            for (int i = 0; i < 8; i++)
#pragma unroll
                for (int p = 0; p < 4; p++) fma2(acc[i][p], a[i], b[p]);
        }
        if (kt < Hn / BK - 1) {
            const int nxt = cur ^ 1;
            As[nxt][lc + 0][lr] = pk(av0.x, av0.x); As[nxt][lc + 1][lr] = pk(av0.y, av0.y);
            As[nxt][lc + 2][lr] = pk(av0.z, av0.z); As[nxt][lc + 3][lr] = pk(av0.w, av0.w);
            As[nxt][lc + 4][lr] = pk(av1.x, av1.x); As[nxt][lc + 5][lr] = pk(av1.y, av1.y);
            As[nxt][lc + 6][lr] = pk(av1.z, av1.z); As[nxt][lc + 7][lr] = pk(av1.w, av1.w);
            Bs[nxt][lc + 0][lr] = bv0.x; Bs[nxt][lc + 1][lr] = bv0.y;
            Bs[nxt][lc + 2][lr] = bv0.z; Bs[nxt][lc + 3][lr] = bv0.w;
            Bs[nxt][lc + 4][lr] = bv1.x; Bs[nxt][lc + 5][lr] = bv1.y;
            Bs[nxt][lc + 6][lr] = bv1.z; Bs[nxt][lc + 7][lr] = bv1.w;
            __syncthreads();
        }
    }

    // ---------------- epilogue ----------------
#pragma unroll
    for (int i = 0; i < 8; i++) {
        int m = bm + ((i < 4) ? (ty * 4 + i) : (64 + ty * 4 + (i - 4)));
        int tokv = 0;
        if (MODE == 1) tokv = tok[m * Sn];
#pragma unroll
        for (int jh = 0; jh < 2; jh++) {
            int n = bn + jh * 64 + tx * 4;
            float2 q0 = up(acc[i][jh * 2]);
            float2 q1 = up(acc[i][jh * 2 + 1]);
            float g0 = q0.x, g1 = q0.y, g2 = q1.x, g3 = q1.y;
            if (MODE == 0) {
                float4 v = {g0, g1, g2, g3};
                *reinterpret_cast<float4*>(Cout + (size_t)m * ldc + n) = v;
            } else if (MODE == 2 && bn >= Gn) {
                float4 v = {g0, g1, g2, g3};
                *reinterpret_cast<float4*>(Cout + (size_t)m * Wn + (n - Gn)) = v;
            } else {
                if (MODE == 1) {
                    const float* pr = P + (size_t)tokv * Gn + n;
                    g0 += pr[0]; g1 += pr[1]; g2 += pr[2]; g3 += pr[3];
                } else {
                    g0 += bias2[n]; g1 += bias2[n + 1]; g2 += bias2[n + 2]; g3 += bias2[n + 3];
                }
                int j = n >> 2;
                float co = cst[m * Hn + j];
                float cn = sigf(g1) * co + sigf(g0) * tanhf(g2);
                float hn = sigf(g3) * tanhf(cn);
                cst[m * Hn + j] = cn;
                hout[m * Hn + j] = hn;
                if (MODE == 1) enc[((size_t)m * Sn + t) * Hn + j] = hn;
            }
        }
    }
}

// ---------------- threefry2x32 (JAX-compatible) ----------------
__device__ __forceinline__ uint32_t rotl32(uint32_t v, int d) { return (v << d) | (v >> (32 - d)); }

__device__ uint32_t threefry_xor(uint32_t k0, uint32_t k1, uint32_t x0, uint32_t x1) {
    uint32_t ks2 = k0 ^ k1 ^ 0x1BD11BDAu;
    x0 += k0; x1 += k1;
    const int ra[4] = {13, 15, 26, 6}, rb[4] = {17, 29, 16, 24};
#pragma unroll
    for (int i = 0; i < 4; i++) { x0 += x1; x1 = rotl32(x1, ra[i]); x1 ^= x0; }
    x0 += k1; x1 += ks2 + 1u;
#pragma unroll
    for (int i = 0; i < 4; i++) { x0 += x1; x1 = rotl32(x1, rb[i]); x1 ^= x0; }
    x0 += ks2; x1 += k0 + 2u;
#pragma unroll
    for (int i = 0; i < 4; i++) { x0 += x1; x1 = rotl32(x1, ra[i]); x1 ^= x0; }
    x0 += k0; x1 += k1 + 3u;
#pragma unroll
    for (int i = 0; i < 4; i++) { x0 += x1; x1 = rotl32(x1, rb[i]); x1 ^= x0; }
    x0 += k1; x1 += ks2 + 4u;
#pragma unroll
    for (int i = 0; i < 4; i++) { x0 += x1; x1 = rotl32(x1, ra[i]); x1 ^= x0; }
    x0 += ks2; x1 += k0 + 5u;
    return x0 ^ x1;  // partitionable 32-bit random_bits = out0 ^ out1
}

__device__ __forceinline__ float gumbel_from_bits(uint32_t bits) {
    const float TINY = 1.17549435e-38f;
    float f = __uint_as_float((bits >> 9) | 0x3f800000u) - 1.0f;  // [0,1)
    float u = f * (1.0f - TINY) + TINY;
    u = fmaxf(TINY, u);
    return -logf(-logf(u));
}

// ---------------- fused scores + masked log-softmax + sample ----------------
__global__ void k_attn(const float* __restrict__ vt, int l,
                       uint32_t key0, uint32_t key1,
                       float* __restrict__ probs, float* __restrict__ tour) {
    int b = blockIdx.x, tid = threadIdx.x;  // 256 threads
    __shared__ float sb[Wn], sv[Wn], ssc[64];
    sb[tid] = g_blend2[b * Wn + tid];
    sv[tid] = vt[tid];
    __syncthreads();
    int warp = tid >> 5, lane = tid & 31;
    for (int s = warp; s < Sn; s += 8) {
        const float* row = g_blend1 + ((size_t)b * Sn + s) * Wn;
        float acc = 0.0f;
#pragma unroll
        for (int q = 0; q < 8; q++) {
            int w = lane + q * 32;
            acc += tanhf(row[w] + sb[w]) * sv[w];
        }
        for (int off = 16; off; off >>= 1) acc += __shfl_xor_sync(0xffffffffu, acc, off);
        if (lane == 0) ssc[s] = acc;
    }
    __syncthreads();
    if (warp != 0) return;
    int s0 = lane, s1 = lane + 32;
    const float NEG = -3.4e38f;
    float x0 = g_mask[b * Sn + s0] ? -100000.0f : ssc[s0];
    float x1 = NEG;
    if (s1 < Sn) x1 = g_mask[b * Sn + s1] ? -100000.0f : ssc[s1];
    float m = fmaxf(x0, x1);
    for (int off = 16; off; off >>= 1) m = fmaxf(m, __shfl_xor_sync(0xffffffffu, m, off));
    float sum = expf(x0 - m) + ((s1 < Sn) ? expf(x1 - m) : 0.0f);
    for (int off = 16; off; off >>= 1) sum += __shfl_xor_sync(0xffffffffu, sum, off);
    float lse = logf(sum);
    float lp0 = x0 - m - lse;
    float lp1 = x1 - m - lse;
    float* prow = probs + ((size_t)b * Ln + l) * Sn;
    prow[s0] = lp0;
    if (s1 < Sn) prow[s1] = lp1;
    float v0 = lp0 + gumbel_from_bits(threefry_xor(key0, key1, 0u, (uint32_t)(b * Sn + s0)));
    float v1 = NEG;
    if (s1 < Sn) v1 = lp1 + gumbel_from_bits(threefry_xor(key0, key1, 0u, (uint32_t)(b * Sn + s1)));
    float bv; int bi;
    if (v1 > v0) { bv = v1; bi = s1; } else { bv = v0; bi = s0; }
    for (int off = 16; off; off >>= 1) {
        float ov = __shfl_xor_sync(0xffffffffu, bv, off);
        int   oi = __shfl_xor_sync(0xffffffffu, bi, off);
        if (ov > bv || (ov == bv && oi < bi)) { bv = ov; bi = oi; }
    }
    if (lane == 0) {
        tour[(size_t)b * Ln + l] = (float)bi;
        g_mask[b * Sn + bi] = 1;
    }
}

// ---------------- host threefry ----------------
static void tf_host(uint32_t k0, uint32_t k1, uint32_t x0, uint32_t x1,
                    uint32_t& o0, uint32_t& o1) {
    uint32_t ks2 = k0 ^ k1 ^ 0x1BD11BDAu;
    x0 += k0; x1 += k1;
    const int ra[4] = {13, 15, 26, 6}, rb[4] = {17, 29, 16, 24};
    auto rl = [](uint32_t v, int d) { return (v << d) | (v >> (32 - d)); };
    for (int i = 0; i < 4; i++) { x0 += x1; x1 = rl(x1, ra[i]); x1 ^= x0; }
    x0 += k1; x1 += ks2 + 1u;
    for (int i = 0; i < 4; i++) { x0 += x1; x1 = rl(x1, rb[i]); x1 ^= x0; }
    x0 += ks2; x1 += k0 + 2u;
    for (int i = 0; i < 4; i++) { x0 += x1; x1 = rl(x1, ra[i]); x1 ^= x0; }
    x0 += k0; x1 += k1 + 3u;
    for (int i = 0; i < 4; i++) { x0 += x1; x1 = rl(x1, rb[i]); x1 ^= x0; }
    x0 += k1; x1 += ks2 + 4u;
    for (int i = 0; i < 4; i++) { x0 += x1; x1 = rl(x1, ra[i]); x1 ^= x0; }
    x0 += ks2; x1 += k0 + 5u;
    o0 = x0; o1 = x1;
}

extern "C" void kernel_launch(void* const* d_in, const int* in_sizes, int n_in,
                              void* d_out, int out_size) {
    const int*   input = (const int*)d_in[0];
    const float* emb   = (const float*)d_in[1];
    const float* eWih  = (const float*)d_in[2];
    const float* eWhh  = (const float*)d_in[3];
    const float* ebih  = (const float*)d_in[4];
    const float* ebhh  = (const float*)d_in[5];
    // d_in[6] = dec_Wih (unused: decoder input is always zero)
    const float* dWhh  = (const float*)d_in[7];
    const float* dbih  = (const float*)d_in[8];
    const float* dbhh  = (const float*)d_in[9];
    const float* W1    = (const float*)d_in[10];
    const float* W2    = (const float*)d_in[11];
    const float* vt    = (const float*)d_in[12];

    float* out   = (float*)d_out;
    float* probs = out;                               // [B, L, S]
    float* tour  = out + (size_t)Bn * Ln * Sn;        // [B, L] as float

    float *p_h0, *p_h1, *p_c, *p_enc, *p_b1, *p_b2, *p_encW2, *p_decW2, *p_bd2, *p_P;
    cudaGetSymbolAddress((void**)&p_h0, g_h0);
    cudaGetSymbolAddress((void**)&p_h1, g_h1);
    cudaGetSymbolAddress((void**)&p_c, g_c);
    cudaGetSymbolAddress((void**)&p_enc, g_enc);
    cudaGetSymbolAddress((void**)&p_b1, g_blend1);
    cudaGetSymbolAddress((void**)&p_b2, g_blend2);
    cudaGetSymbolAddress((void**)&p_encW2, g_encW2);
    cudaGetSymbolAddress((void**)&p_decW2, g_decW2);
    cudaGetSymbolAddress((void**)&p_bd2, g_bias_dec2);
    cudaGetSymbolAddress((void**)&p_P, g_P);

    const int BHB = (Bn * Hn + 255) / 256;

    k_prep<<<(ND * Hn + 255) / 256, 256>>>(eWhh, dWhh, dbih, dbhh, W2);
    k_prep_P<<<(Vn * Gn + 255) / 256, 256>>>(emb, eWih, ebih, ebhh);
    k_init<<<BHB, 256>>>();

    // -------- encoder: 50 fused GEMM+cell steps, K=512 --------
    for (int t = 0; t < Sn; t++) {
        float* hin  = (t & 1) ? p_h1 : p_h0;
        float* hout = (t & 1) ? p_h0 : p_h1;
        gemm_fused<1><<<dim3(Gn / 128, Bn / 128), 256>>>(
            hin, p_encW2, nullptr, p_P, input + t,
            nullptr, 0, hout, p_c, p_enc, t);
    }

    // -------- blend1 = enc_states @ W1^T : [B*S, W] --------
    gemm_fused<0><<<dim3(Wn / 128, (Bn * Sn) / 128), 256>>>(
        p_enc, W1, nullptr, nullptr, nullptr,
        p_b1, Wn, nullptr, nullptr, nullptr, 0);

    // -------- decoder first cell (h_prev = 0) --------
    k_dec0<<<BHB, 256>>>();

    // step keys: keys[l] = threefry2x32((0,42), (0,l))
    uint32_t K0[Ln], K1[Ln];
    for (int l = 0; l < Ln; l++) tf_host(0u, 42u, 0u, (uint32_t)l, K0[l], K1[l]);

    for (int l = 0; l < Ln; l++) {
        float* hin  = (l & 1) ? p_h1 : p_h0;
        float* hout = (l & 1) ? p_h0 : p_h1;
        // [gates_{l+2} | blend2_l] = h @ [decWhh_int; W2]^T ; cell fused
        gemm_fused<2><<<dim3(ND / 128, Bn / 128), 256>>>(
            hin, p_decW2, p_bd2, nullptr, nullptr,
            p_b2, Wn, hout, p_c, nullptr, 0);
        k_attn<<<Bn, 256>>>(vt, l, K0[l], K1[l], probs, tour);
    }
    (void)in_sizes; (void)n_in; (void)out_size;
}

// round 4
// speedup vs baseline: 1.0567x; 1.0567x over previous
#include <cuda_runtime.h>
#include <cstdint>
#include <math.h>

typedef unsigned long long ull;

// Problem constants
#define Bn 2048
#define Sn 50
#define En 256
#define Hn 512
#define Gn 2048        // 4*H
#define Wn 256
#define Ln 50
#define ND (Gn + Wn)   // 2304 : [interleaved dec gates | W2 rows]
#define Vn 51

// ---------------- device scratch (no allocations allowed) ----------------
__device__ float g_h0[Bn * Hn];
__device__ float g_h1[Bn * Hn];
__device__ float g_c[Bn * Hn];
__device__ float g_enc[(size_t)Bn * Sn * Hn];     // encoder hidden states [B,S,H]
__device__ float g_blend1[(size_t)Bn * Sn * Wn];  // [B,S,W]
__device__ float g_blend2[Bn * Wn];
__device__ unsigned char g_mask[Bn * Sn];
__device__ float g_encW2[Gn * Hn];                // interleaved [4j+g, k] of enc_Whh
__device__ float g_decW2[ND * Hn];                // interleaved dec_Whh rows then W2 rows
__device__ float g_bias_dec2[Gn];                 // interleaved decoder bias
__device__ float g_P[Vn * Gn];                    // emb@Wih^T + enc bias, interleaved cols

// ---------------- f32x2 helpers ----------------
__device__ __forceinline__ ull pk(float x, float y) {
    ull r; asm("mov.b64 %0,{%1,%2};" : "=l"(r) : "f"(x), "f"(y)); return r;
}
__device__ __forceinline__ void fma2(ull& d, ull a, ull b) {
    asm("fma.rn.f32x2 %0,%1,%2,%3;" : "=l"(d) : "l"(a), "l"(b), "l"(d));
}
__device__ __forceinline__ float2 up(ull v) {
    float2 f; asm("mov.b64 {%0,%1},%2;" : "=f"(f.x), "=f"(f.y) : "l"(v)); return f;
}

__device__ __forceinline__ float sigf(float x) { return 1.0f / (1.0f + expf(-x)); }

// ---------------- prep: weight reorder + interleave ----------------
__global__ void k_prep(const float* __restrict__ eWhh,
                       const float* __restrict__ dWhh, const float* __restrict__ dbih,
                       const float* __restrict__ dbhh, const float* __restrict__ W2) {
    int idx = blockIdx.x * blockDim.x + threadIdx.x;
    if (idx < Gn * Hn) {
        int n2 = idx / Hn, k = idx % Hn;
        int g = n2 & 3, j = n2 >> 2;
        g_encW2[idx] = eWhh[(g * Hn + j) * Hn + k];
    }
    if (idx < ND * Hn) {
        int n2 = idx / Hn, k = idx % Hn;
        if (n2 < Gn) {
            int g = n2 & 3, j = n2 >> 2;
            g_decW2[idx] = dWhh[(g * Hn + j) * Hn + k];
        } else {
            g_decW2[idx] = W2[(size_t)(n2 - Gn) * Hn + k];
        }
    }
    if (idx < Gn) {
        int g = idx & 3, j = idx >> 2;
        int r = g * Hn + j;
        g_bias_dec2[idx] = dbih[r] + dbhh[r];
    }
}

// P[v][n2] = emb[v] . Wih[r] + bih[r] + bhh[r],  r = (n2&3)*H + (n2>>2)
__global__ void k_prep_P(const float* __restrict__ emb, const float* __restrict__ eWih,
                         const float* __restrict__ ebih, const float* __restrict__ ebhh) {
    int idx = blockIdx.x * blockDim.x + threadIdx.x;
    if (idx >= Vn * Gn) return;
    int v = idx / Gn, n2 = idx % Gn;
    int g = n2 & 3, j = n2 >> 2;
    int r = g * Hn + j;
    const float4* e = reinterpret_cast<const float4*>(emb + (size_t)v * En);
    const float4* w = reinterpret_cast<const float4*>(eWih + (size_t)r * En);
    float s = 0.0f;
    #pragma unroll 8
    for (int k = 0; k < En / 4; k++) {
        float4 a = __ldg(e + k), b = __ldg(w + k);
        s += a.x * b.x + a.y * b.y + a.z * b.z + a.w * b.w;
    }
    g_P[idx] = s + ebih[r] + ebhh[r];
}

__global__ void k_init() {
    int idx = blockIdx.x * blockDim.x + threadIdx.x;
    if (idx < Bn * Hn) { g_h0[idx] = 0.0f; g_c[idx] = 0.0f; }
    if (idx < Bn * Sn) g_mask[idx] = 0;
}

// decoder first cell: h_prev = 0 -> gates = bias only; c0 = enc last hidden
__global__ void k_dec0() {
    int idx = blockIdx.x * blockDim.x + threadIdx.x;
    if (idx >= Bn * Hn) return;
    int b = idx / Hn, j = idx % Hn;
    float gi = g_bias_dec2[4 * j + 0], gf = g_bias_dec2[4 * j + 1];
    float gg = g_bias_dec2[4 * j + 2], go = g_bias_dec2[4 * j + 3];
    float c0 = g_enc[((size_t)b * Sn + (Sn - 1)) * Hn + j];
    float cn = sigf(gf) * c0 + sigf(gi) * tanhf(gg);
    g_c[idx] = cn;
    g_h0[idx] = sigf(go) * tanhf(cn);
}

// ---------------- fused GEMM (FFMA2, BK=8, dup-A smem, double-buffered) ----
// C[M,N] = A[M,512] * Bw[N,512]^T ; epilogue per MODE:
//   MODE 0: plain store to Cout (ldc)
//   MODE 1: encoder: add P[token], LSTM cell -> hout, cst, enc[:,t,:]
//   MODE 2: decoder: bn<Gn -> add bias2 + cell -> hout,cst ; bn>=Gn -> store blend2
template <int MODE>
__global__ __launch_bounds__(256, 2) void gemm_fused(
    const float* __restrict__ A,
    const float* __restrict__ Bw,
    const float* __restrict__ bias2,
    const float* __restrict__ P,
    const int* __restrict__ tok,
    float* __restrict__ Cout, int ldc,
    float* __restrict__ hout,
    float* __restrict__ cst,
    float* __restrict__ enc, int t) {
    __shared__ ull   As[2][8][128];   // A duplicated into both f32x2 lanes
    __shared__ float Bs[2][8][128];   // plain floats; adjacent pair == packed operand
    const int tid = threadIdx.x;
    const int bm = blockIdx.y * 128, bn = blockIdx.x * 128;
    const int lr = tid >> 1;           // 0..127 : tile row
    const int lc = (tid & 1) << 2;     // 0 or 4 : k offset
    const int tx = tid & 15, ty = tid >> 4;
    const float* Aa = A + (size_t)(bm + lr) * Hn + lc;
    const float* Bb = Bw + (size_t)(bn + lr) * Hn + lc;

    ull acc[8][4];
#pragma unroll
    for (int i = 0; i < 8; i++)
#pragma unroll
        for (int p = 0; p < 4; p++) acc[i][p] = 0ull;

    float4 av = *reinterpret_cast<const float4*>(Aa);
    float4 bv = *reinterpret_cast<const float4*>(Bb);
    {
        As[0][lc + 0][lr] = pk(av.x, av.x); As[0][lc + 1][lr] = pk(av.y, av.y);
        As[0][lc + 2][lr] = pk(av.z, av.z); As[0][lc + 3][lr] = pk(av.w, av.w);
        Bs[0][lc + 0][lr] = bv.x; Bs[0][lc + 1][lr] = bv.y;
        Bs[0][lc + 2][lr] = bv.z; Bs[0][lc + 3][lr] = bv.w;
    }
    __syncthreads();

#pragma unroll 1
    for (int kt = 0; kt < Hn / 8; kt++) {
        const int cur = kt & 1;
        if (kt < Hn / 8 - 1) {
            av = *reinterpret_cast<const float4*>(Aa + (kt + 1) * 8);
            bv = *reinterpret_cast<const float4*>(Bb + (kt + 1) * 8);
        }
#pragma unroll
        for (int kk = 0; kk < 8; kk++) {
            ulonglong2 aA = *reinterpret_cast<const ulonglong2*>(&As[cur][kk][ty * 4]);
            ulonglong2 aB = *reinterpret_cast<const ulonglong2*>(&As[cur][kk][ty * 4 + 2]);
            ulonglong2 aC = *reinterpret_cast<const ulonglong2*>(&As[cur][kk][64 + ty * 4]);
            ulonglong2 aD = *reinterpret_cast<const ulonglong2*>(&As[cur][kk][64 + ty * 4 + 2]);
            ulonglong2 bp0 = *reinterpret_cast<const ulonglong2*>(&Bs[cur][kk][tx * 4]);
            ulonglong2 bp1 = *reinterpret_cast<const ulonglong2*>(&Bs[cur][kk][64 + tx * 4]);
            ull a[8] = {aA.x, aA.y, aB.x, aB.y, aC.x, aC.y, aD.x, aD.y};
            ull b[4] = {bp0.x, bp0.y, bp1.x, bp1.y};
#pragma unroll
            for (int i = 0; i < 8; i++)
#pragma unroll
                for (int p = 0; p < 4; p++) fma2(acc[i][p], a[i], b[p]);
        }
        if (kt < Hn / 8 - 1) {
            const int nxt = cur ^ 1;
            As[nxt][lc + 0][lr] = pk(av.x, av.x); As[nxt][lc + 1][lr] = pk(av.y, av.y);
            As[nxt][lc + 2][lr] = pk(av.z, av.z); As[nxt][lc + 3][lr] = pk(av.w, av.w);
            Bs[nxt][lc + 0][lr] = bv.x; Bs[nxt][lc + 1][lr] = bv.y;
            Bs[nxt][lc + 2][lr] = bv.z; Bs[nxt][lc + 3][lr] = bv.w;
            __syncthreads();
        }
    }

    // ---------------- epilogue ----------------
#pragma unroll
    for (int i = 0; i < 8; i++) {
        int m = bm + ((i < 4) ? (ty * 4 + i) : (64 + ty * 4 + (i - 4)));
        int tokv = 0;
        if (MODE == 1) tokv = tok[m * Sn];
#pragma unroll
        for (int jh = 0; jh < 2; jh++) {
            int n = bn + jh * 64 + tx * 4;
            float2 q0 = up(acc[i][jh * 2]);
            float2 q1 = up(acc[i][jh * 2 + 1]);
            float g0 = q0.x, g1 = q0.y, g2 = q1.x, g3 = q1.y;
            if (MODE == 0) {
                float4 v = {g0, g1, g2, g3};
                *reinterpret_cast<float4*>(Cout + (size_t)m * ldc + n) = v;
            } else if (MODE == 2 && bn >= Gn) {
                float4 v = {g0, g1, g2, g3};
                *reinterpret_cast<float4*>(Cout + (size_t)m * Wn + (n - Gn)) = v;
            } else {
                if (MODE == 1) {
                    const float* pr = P + (size_t)tokv * Gn + n;
                    g0 += pr[0]; g1 += pr[1]; g2 += pr[2]; g3 += pr[3];
                } else {
                    g0 += bias2[n]; g1 += bias2[n + 1]; g2 += bias2[n + 2]; g3 += bias2[n + 3];
                }
                int j = n >> 2;
                float co = cst[m * Hn + j];
                float cn = sigf(g1) * co + sigf(g0) * tanhf(g2);
                float hn = sigf(g3) * tanhf(cn);
                cst[m * Hn + j] = cn;
                hout[m * Hn + j] = hn;
                if (MODE == 1) enc[((size_t)m * Sn + t) * Hn + j] = hn;
            }
        }
    }
}

// ---------------- threefry2x32 (JAX-compatible) ----------------
__device__ __forceinline__ uint32_t rotl32(uint32_t v, int d) { return (v << d) | (v >> (32 - d)); }

__device__ uint32_t threefry_xor(uint32_t k0, uint32_t k1, uint32_t x0, uint32_t x1) {
    uint32_t ks2 = k0 ^ k1 ^ 0x1BD11BDAu;
    x0 += k0; x1 += k1;
    const int ra[4] = {13, 15, 26, 6}, rb[4] = {17, 29, 16, 24};
#pragma unroll
    for (int i = 0; i < 4; i++) { x0 += x1; x1 = rotl32(x1, ra[i]); x1 ^= x0; }
    x0 += k1; x1 += ks2 + 1u;
#pragma unroll
    for (int i = 0; i < 4; i++) { x0 += x1; x1 = rotl32(x1, rb[i]); x1 ^= x0; }
    x0 += ks2; x1 += k0 + 2u;
#pragma unroll
    for (int i = 0; i < 4; i++) { x0 += x1; x1 = rotl32(x1, ra[i]); x1 ^= x0; }
    x0 += k0; x1 += k1 + 3u;
#pragma unroll
    for (int i = 0; i < 4; i++) { x0 += x1; x1 = rotl32(x1, rb[i]); x1 ^= x0; }
    x0 += k1; x1 += ks2 + 4u;
#pragma unroll
    for (int i = 0; i < 4; i++) { x0 += x1; x1 = rotl32(x1, ra[i]); x1 ^= x0; }
    x0 += ks2; x1 += k0 + 5u;
    return x0 ^ x1;  // partitionable 32-bit random_bits = out0 ^ out1
}

__device__ __forceinline__ float gumbel_from_bits(uint32_t bits) {
    const float TINY = 1.17549435e-38f;
    float f = __uint_as_float((bits >> 9) | 0x3f800000u) - 1.0f;  // [0,1)
    float u = f * (1.0f - TINY) + TINY;
    u = fmaxf(TINY, u);
    return -logf(-logf(u));
}

// ---------------- fused scores + masked log-softmax + sample ----------------
__global__ void k_attn(const float* __restrict__ vt, int l,
                       uint32_t key0, uint32_t key1,
                       float* __restrict__ probs, float* __restrict__ tour) {
    int b = blockIdx.x, tid = threadIdx.x;  // 256 threads
    __shared__ float sb[Wn], sv[Wn], ssc[64];
    sb[tid] = g_blend2[b * Wn + tid];
    sv[tid] = vt[tid];
    __syncthreads();
    int warp = tid >> 5, lane = tid & 31;
    for (int s = warp; s < Sn; s += 8) {
        const float* row = g_blend1 + ((size_t)b * Sn + s) * Wn;
        float acc = 0.0f;
#pragma unroll
        for (int q = 0; q < 8; q++) {
            int w = lane + q * 32;
            acc += tanhf(row[w] + sb[w]) * sv[w];
        }
        for (int off = 16; off; off >>= 1) acc += __shfl_xor_sync(0xffffffffu, acc, off);
        if (lane == 0) ssc[s] = acc;
    }
    __syncthreads();
    if (warp != 0) return;
    int s0 = lane, s1 = lane + 32;
    const float NEG = -3.4e38f;
    float x0 = g_mask[b * Sn + s0] ? -100000.0f : ssc[s0];
    float x1 = NEG;
    if (s1 < Sn) x1 = g_mask[b * Sn + s1] ? -100000.0f : ssc[s1];
    float m = fmaxf(x0, x1);
    for (int off = 16; off; off >>= 1) m = fmaxf(m, __shfl_xor_sync(0xffffffffu, m, off));
    float sum = expf(x0 - m) + ((s1 < Sn) ? expf(x1 - m) : 0.0f);
    for (int off = 16; off; off >>= 1) sum += __shfl_xor_sync(0xffffffffu, sum, off);
    float lse = logf(sum);
    float lp0 = x0 - m - lse;
    float lp1 = x1 - m - lse;
    float* prow = probs + ((size_t)b * Ln + l) * Sn;
    prow[s0] = lp0;
    if (s1 < Sn) prow[s1] = lp1;
    float v0 = lp0 + gumbel_from_bits(threefry_xor(key0, key1, 0u, (uint32_t)(b * Sn + s0)));
    float v1 = NEG;
    if (s1 < Sn) v1 = lp1 + gumbel_from_bits(threefry_xor(key0, key1, 0u, (uint32_t)(b * Sn + s1)));
    float bv; int bi;
    if (v1 > v0) { bv = v1; bi = s1; } else { bv = v0; bi = s0; }
    for (int off = 16; off; off >>= 1) {
        float ov = __shfl_xor_sync(0xffffffffu, bv, off);
        int   oi = __shfl_xor_sync(0xffffffffu, bi, off);
        if (ov > bv || (ov == bv && oi < bi)) { bv = ov; bi = oi; }
    }
    if (lane == 0) {
        tour[(size_t)b * Ln + l] = (float)bi;
        g_mask[b * Sn + bi] = 1;
    }
}

// ---------------- host threefry ----------------
static void tf_host(uint32_t k0, uint32_t k1, uint32_t x0, uint32_t x1,
                    uint32_t& o0, uint32_t& o1) {
    uint32_t ks2 = k0 ^ k1 ^ 0x1BD11BDAu;
    x0 += k0; x1 += k1;
    const int ra[4] = {13, 15, 26, 6}, rb[4] = {17, 29, 16, 24};
    auto rl = [](uint32_t v, int d) { return (v << d) | (v >> (32 - d)); };
    for (int i = 0; i < 4; i++) { x0 += x1; x1 = rl(x1, ra[i]); x1 ^= x0; }
    x0 += k1; x1 += ks2 + 1u;
    for (int i = 0; i < 4; i++) { x0 += x1; x1 = rl(x1, rb[i]); x1 ^= x0; }
    x0 += ks2; x1 += k0 + 2u;
    for (int i = 0; i < 4; i++) { x0 += x1; x1 = rl(x1, ra[i]); x1 ^= x0; }
    x0 += k0; x1 += k1 + 3u;
    for (int i = 0; i < 4; i++) { x0 += x1; x1 = rl(x1, rb[i]); x1 ^= x0; }
    x0 += k1; x1 += ks2 + 4u;
    for (int i = 0; i < 4; i++) { x0 += x1; x1 = rl(x1, ra[i]); x1 ^= x0; }
    x0 += ks2; x1 += k0 + 5u;
    o0 = x0; o1 = x1;
}

extern "C" void kernel_launch(void* const* d_in, const int* in_sizes, int n_in,
                              void* d_out, int out_size) {
    const int*   input = (const int*)d_in[0];
    const float* emb   = (const float*)d_in[1];
    const float* eWih  = (const float*)d_in[2];
    const float* eWhh  = (const float*)d_in[3];
    const float* ebih  = (const float*)d_in[4];
    const float* ebhh  = (const float*)d_in[5];
    // d_in[6] = dec_Wih (unused: decoder input is always zero)
    const float* dWhh  = (const float*)d_in[7];
    const float* dbih  = (const float*)d_in[8];
    const float* dbhh  = (const float*)d_in[9];
    const float* W1    = (const float*)d_in[10];
    const float* W2    = (const float*)d_in[11];
    const float* vt    = (const float*)d_in[12];

    float* out   = (float*)d_out;
    float* probs = out;                               // [B, L, S]
    float* tour  = out + (size_t)Bn * Ln * Sn;        // [B, L] as float

    float *p_h0, *p_h1, *p_c, *p_enc, *p_b1, *p_b2, *p_encW2, *p_decW2, *p_bd2, *p_P;
    cudaGetSymbolAddress((void**)&p_h0, g_h0);
    cudaGetSymbolAddress((void**)&p_h1, g_h1);
    cudaGetSymbolAddress((void**)&p_c, g_c);
    cudaGetSymbolAddress((void**)&p_enc, g_enc);
    cudaGetSymbolAddress((void**)&p_b1, g_blend1);
    cudaGetSymbolAddress((void**)&p_b2, g_blend2);
    cudaGetSymbolAddress((void**)&p_encW2, g_encW2);
    cudaGetSymbolAddress((void**)&p_decW2, g_decW2);
    cudaGetSymbolAddress((void**)&p_bd2, g_bias_dec2);
    cudaGetSymbolAddress((void**)&p_P, g_P);

    const int BHB = (Bn * Hn + 255) / 256;

    k_prep<<<(ND * Hn + 255) / 256, 256>>>(eWhh, dWhh, dbih, dbhh, W2);
    k_prep_P<<<(Vn * Gn + 255) / 256, 256>>>(emb, eWih, ebih, ebhh);
    k_init<<<BHB, 256>>>();

    // -------- encoder: 50 fused GEMM+cell steps, K=512 --------
    for (int t = 0; t < Sn; t++) {
        float* hin  = (t & 1) ? p_h1 : p_h0;
        float* hout = (t & 1) ? p_h0 : p_h1;
        gemm_fused<1><<<dim3(Gn / 128, Bn / 128), 256>>>(
            hin, p_encW2, nullptr, p_P, input + t,
            nullptr, 0, hout, p_c, p_enc, t);
    }

    // -------- blend1 = enc_states @ W1^T : [B*S, W] --------
    gemm_fused<0><<<dim3(Wn / 128, (Bn * Sn) / 128), 256>>>(
        p_enc, W1, nullptr, nullptr, nullptr,
        p_b1, Wn, nullptr, nullptr, nullptr, 0);

    // -------- decoder first cell (h_prev = 0) --------
    k_dec0<<<BHB, 256>>>();

    // step keys: keys[l] = threefry2x32((0,42), (0,l))
    uint32_t K0[Ln], K1[Ln];
    for (int l = 0; l < Ln; l++) tf_host(0u, 42u, 0u, (uint32_t)l, K0[l], K1[l]);

    for (int l = 0; l < Ln; l++) {
        float* hin  = (l & 1) ? p_h1 : p_h0;
        float* hout = (l & 1) ? p_h0 : p_h1;
        // [gates_{l+2} | blend2_l] = h @ [decWhh_int; W2]^T ; cell fused
        gemm_fused<2><<<dim3(ND / 128, Bn / 128), 256>>>(
            hin, p_decW2, p_bd2, nullptr, nullptr,
            p_b2, Wn, hout, p_c, nullptr, 0);
        k_attn<<<Bn, 256>>>(vt, l, K0[l], K1[l], probs, tour);
    }
    (void)in_sizes; (void)n_in; (void)out_size;
}

// round 5
// speedup vs baseline: 1.1675x; 1.1048x over previous
#include <cuda_runtime.h>
#include <cstdint>
#include <math.h>

typedef unsigned long long ull;

// Problem constants
#define Bn 2048
#define Sn 50
#define En 256
#define Hn 512
#define Gn 2048        // 4*H
#define Wn 256
#define Ln 50
#define ND (Gn + Wn)   // 2304 : [interleaved dec gates | W2 rows]
#define Vn 51
#define BSn (Bn * Sn)
#define NKT (Hn / 16)

// ---------------- device scratch (K-major layouts) ----------------
__device__ float g_hT0[Hn * Bn];                  // h transposed [j][b]
__device__ float g_hT1[Hn * Bn];
__device__ float g_cT[Hn * Bn];
__device__ float g_encT[(size_t)Hn * BSn];        // [j][b*S+s]
__device__ float g_blend1[(size_t)BSn * Wn];      // [b*S+s][w] row-major
__device__ float g_blend2[Bn * Wn];
__device__ unsigned char g_mask[Bn * Sn];
__device__ float g_encW2T[Hn * Gn];               // [k][n2] n2=4j+g
__device__ float g_decW2T[Hn * ND];               // [k][n2] (gates | W2)
__device__ float g_W1T[Hn * Wn];                  // [k][w]
__device__ float g_bias_dec2[Gn];
__device__ float g_P[Vn * Gn];                    // emb@Wih^T + enc bias (interleaved n2)

// ---------------- f32x2 helpers ----------------
__device__ __forceinline__ ull pk(float x, float y) {
    ull r; asm("mov.b64 %0,{%1,%2};" : "=l"(r) : "f"(x), "f"(y)); return r;
}
__device__ __forceinline__ void fma2(ull& d, ull a, ull b) {
    asm("fma.rn.f32x2 %0,%1,%2,%3;" : "=l"(d) : "l"(a), "l"(b), "l"(d));
}
__device__ __forceinline__ float2 up(ull v) {
    float2 f; asm("mov.b64 {%0,%1},%2;" : "=f"(f.x), "=f"(f.y) : "l"(v)); return f;
}
__device__ __forceinline__ void cp16(uint32_t dst, const float* src) {
    asm volatile("cp.async.cg.shared.global [%0], [%1], 16;\n" :: "r"(dst), "l"(src));
}
__device__ __forceinline__ float sigf(float x) { return 1.0f / (1.0f + expf(-x)); }

// ---------------- prep: K-major weight builds ----------------
__global__ void k_prep(const float* __restrict__ eWhh,
                       const float* __restrict__ dWhh, const float* __restrict__ dbih,
                       const float* __restrict__ dbhh, const float* __restrict__ W2,
                       const float* __restrict__ W1) {
    int idx = blockIdx.x * blockDim.x + threadIdx.x;
    if (idx < Hn * Gn) {
        int k = idx / Gn, n2 = idx % Gn;
        int g = n2 & 3, j = n2 >> 2;
        g_encW2T[idx] = eWhh[(g * Hn + j) * Hn + k];
    }
    if (idx < Hn * ND) {
        int k = idx / ND, n2 = idx % ND;
        if (n2 < Gn) {
            int g = n2 & 3, j = n2 >> 2;
            g_decW2T[idx] = dWhh[(g * Hn + j) * Hn + k];
        } else {
            g_decW2T[idx] = W2[(size_t)(n2 - Gn) * Hn + k];
        }
    }
    if (idx < Hn * Wn) {
        int k = idx / Wn, w = idx % Wn;
        g_W1T[idx] = W1[w * Hn + k];
    }
    if (idx < Gn) {
        int g = idx & 3, j = idx >> 2;
        int r = g * Hn + j;
        g_bias_dec2[idx] = dbih[r] + dbhh[r];
    }
}

// P[v][n2] = emb[v] . Wih[r] + bih[r] + bhh[r],  r = (n2&3)*H + (n2>>2)
__global__ void k_prep_P(const float* __restrict__ emb, const float* __restrict__ eWih,
                         const float* __restrict__ ebih, const float* __restrict__ ebhh) {
    int idx = blockIdx.x * blockDim.x + threadIdx.x;
    if (idx >= Vn * Gn) return;
    int v = idx / Gn, n2 = idx % Gn;
    int g = n2 & 3, j = n2 >> 2;
    int r = g * Hn + j;
    const float4* e = reinterpret_cast<const float4*>(emb + (size_t)v * En);
    const float4* w = reinterpret_cast<const float4*>(eWih + (size_t)r * En);
    float s = 0.0f;
    #pragma unroll 8
    for (int k = 0; k < En / 4; k++) {
        float4 a = __ldg(e + k), b = __ldg(w + k);
        s += a.x * b.x + a.y * b.y + a.z * b.z + a.w * b.w;
    }
    g_P[idx] = s + ebih[r] + ebhh[r];
}

__global__ void k_init() {
    int idx = blockIdx.x * blockDim.x + threadIdx.x;
    if (idx < Bn * Hn) { g_hT0[idx] = 0.0f; g_cT[idx] = 0.0f; }
    if (idx < Bn * Sn) g_mask[idx] = 0;
}

// decoder first cell: h_prev = 0 -> gates = bias only; c0 = enc last hidden
__global__ void k_dec0() {
    int idx = blockIdx.x * blockDim.x + threadIdx.x;
    if (idx >= Bn * Hn) return;
    int j = idx / Bn, b = idx % Bn;
    float gi = g_bias_dec2[4 * j + 0], gf = g_bias_dec2[4 * j + 1];
    float gg = g_bias_dec2[4 * j + 2], go = g_bias_dec2[4 * j + 3];
    float c0 = g_encT[(size_t)j * BSn + b * Sn + (Sn - 1)];
    float cn = sigf(gf) * c0 + sigf(gi) * tanhf(gg);
    g_cT[j * Bn + b] = cn;
    g_hT0[j * Bn + b] = sigf(go) * tanhf(cn);
}

// ---------------- fused GEMM (FFMA2, cp.async, K-major operands) -----------
// C[M,N] = sum_k A[k][m] * Bw[k][n] ; epilogue per MODE:
//   MODE 0: plain row-major store to Cout (ldc)
//   MODE 1: encoder: add P[token], LSTM cell -> hT, cT, encT[:, m*Sn+t]
//   MODE 2: decoder: bn<Gn -> bias2 + cell -> hT,cT ; bn>=Gn -> blend2 row-major
template <int MODE>
__global__ __launch_bounds__(256, 2) void gemm_fused(
    const float* __restrict__ A, int ldA,
    const float* __restrict__ Bw, int ldB,
    const float* __restrict__ bias2,
    const float* __restrict__ P,
    const int* __restrict__ tok,
    float* __restrict__ Cout, int ldc,
    float* __restrict__ houtT,
    float* __restrict__ cstT,
    float* __restrict__ encT, int t) {
    __shared__ float As[2][16][128];
    __shared__ float Bs[2][16][128];
    const int tid = threadIdx.x;
    const int bm = blockIdx.y * 128, bn = blockIdx.x * 128;
    const int tx = tid & 15, ty = tid >> 4;
    // cp.async chunk coords: 512 16B-chunks per (16x128) tile, 2 per thread
    const int ck = tid >> 5;          // k row (0..7), second chunk at +8
    const int cc = (tid & 31) * 4;    // col within row

    const float* Ag = A + (size_t)ck * ldA + bm + cc;
    const float* Bg = Bw + (size_t)ck * ldB + bn + cc;

    ull acc[8][4];
#pragma unroll
    for (int i = 0; i < 8; i++)
#pragma unroll
        for (int p = 0; p < 4; p++) acc[i][p] = 0ull;

    // issue tile 0
    {
        cp16((uint32_t)__cvta_generic_to_shared(&As[0][ck][cc]), Ag);
        cp16((uint32_t)__cvta_generic_to_shared(&As[0][ck + 8][cc]), Ag + 8 * ldA);
        cp16((uint32_t)__cvta_generic_to_shared(&Bs[0][ck][cc]), Bg);
        cp16((uint32_t)__cvta_generic_to_shared(&Bs[0][ck + 8][cc]), Bg + 8 * ldB);
        asm volatile("cp.async.commit_group;\n");
    }

#pragma unroll 1
    for (int kt = 0; kt < NKT; kt++) {
        const int cur = kt & 1;
        asm volatile("cp.async.wait_group 0;\n");
        __syncthreads();
        if (kt + 1 < NKT) {
            const int nxt = cur ^ 1;
            const float* ag = Ag + (size_t)(kt + 1) * 16 * ldA;
            const float* bg = Bg + (size_t)(kt + 1) * 16 * ldB;
            cp16((uint32_t)__cvta_generic_to_shared(&As[nxt][ck][cc]), ag);
            cp16((uint32_t)__cvta_generic_to_shared(&As[nxt][ck + 8][cc]), ag + 8 * ldA);
            cp16((uint32_t)__cvta_generic_to_shared(&Bs[nxt][ck][cc]), bg);
            cp16((uint32_t)__cvta_generic_to_shared(&Bs[nxt][ck + 8][cc]), bg + 8 * ldB);
            asm volatile("cp.async.commit_group;\n");
        }
#pragma unroll
        for (int kk = 0; kk < 16; kk++) {
            float4 aq0 = *reinterpret_cast<const float4*>(&As[cur][kk][ty * 4]);
            float4 aq1 = *reinterpret_cast<const float4*>(&As[cur][kk][64 + ty * 4]);
            ulonglong2 bp0 = *reinterpret_cast<const ulonglong2*>(&Bs[cur][kk][tx * 4]);
            ulonglong2 bp1 = *reinterpret_cast<const ulonglong2*>(&Bs[cur][kk][64 + tx * 4]);
            ull a[8] = {pk(aq0.x, aq0.x), pk(aq0.y, aq0.y), pk(aq0.z, aq0.z), pk(aq0.w, aq0.w),
                        pk(aq1.x, aq1.x), pk(aq1.y, aq1.y), pk(aq1.z, aq1.z), pk(aq1.w, aq1.w)};
            ull b[4] = {bp0.x, bp0.y, bp1.x, bp1.y};
#pragma unroll
            for (int i = 0; i < 8; i++)
#pragma unroll
                for (int p = 0; p < 4; p++) fma2(acc[i][p], a[i], b[p]);
        }
    }

    // ---------------- epilogue ----------------
#pragma unroll
    for (int i = 0; i < 8; i++) {
        int m = bm + ((i < 4) ? (ty * 4 + i) : (64 + ty * 4 + (i - 4)));
        int tokv = 0;
        if (MODE == 1) tokv = tok[m * Sn];
#pragma unroll
        for (int jh = 0; jh < 2; jh++) {
            int n = bn + jh * 64 + tx * 4;
            float2 q0 = up(acc[i][jh * 2]);
            float2 q1 = up(acc[i][jh * 2 + 1]);
            float g0 = q0.x, g1 = q0.y, g2 = q1.x, g3 = q1.y;
            if (MODE == 0) {
                float4 v = {g0, g1, g2, g3};
                *reinterpret_cast<float4*>(Cout + (size_t)m * ldc + n) = v;
            } else if (MODE == 2 && bn >= Gn) {
                float4 v = {g0, g1, g2, g3};
                *reinterpret_cast<float4*>(Cout + (size_t)m * Wn + (n - Gn)) = v;
            } else {
                if (MODE == 1) {
                    const float* pr = P + (size_t)tokv * Gn + n;
                    g0 += pr[0]; g1 += pr[1]; g2 += pr[2]; g3 += pr[3];
                } else {
                    g0 += bias2[n]; g1 += bias2[n + 1]; g2 += bias2[n + 2]; g3 += bias2[n + 3];
                }
                int j = n >> 2;
                float co = cstT[j * Bn + m];
                float cn = sigf(g1) * co + sigf(g0) * tanhf(g2);
                float hn = sigf(g3) * tanhf(cn);
                cstT[j * Bn + m] = cn;
                houtT[j * Bn + m] = hn;
                if (MODE == 1) encT[(size_t)j * BSn + m * Sn + t] = hn;
            }
        }
    }
}

// ---------------- threefry2x32 (JAX-compatible) ----------------
__device__ __forceinline__ uint32_t rotl32(uint32_t v, int d) { return (v << d) | (v >> (32 - d)); }

__device__ uint32_t threefry_xor(uint32_t k0, uint32_t k1, uint32_t x0, uint32_t x1) {
    uint32_t ks2 = k0 ^ k1 ^ 0x1BD11BDAu;
    x0 += k0; x1 += k1;
    const int ra[4] = {13, 15, 26, 6}, rb[4] = {17, 29, 16, 24};
#pragma unroll
    for (int i = 0; i < 4; i++) { x0 += x1; x1 = rotl32(x1, ra[i]); x1 ^= x0; }
    x0 += k1; x1 += ks2 + 1u;
#pragma unroll
    for (int i = 0; i < 4; i++) { x0 += x1; x1 = rotl32(x1, rb[i]); x1 ^= x0; }
    x0 += ks2; x1 += k0 + 2u;
#pragma unroll
    for (int i = 0; i < 4; i++) { x0 += x1; x1 = rotl32(x1, ra[i]); x1 ^= x0; }
    x0 += k0; x1 += k1 + 3u;
#pragma unroll
    for (int i = 0; i < 4; i++) { x0 += x1; x1 = rotl32(x1, rb[i]); x1 ^= x0; }
    x0 += k1; x1 += ks2 + 4u;
#pragma unroll
    for (int i = 0; i < 4; i++) { x0 += x1; x1 = rotl32(x1, ra[i]); x1 ^= x0; }
    x0 += ks2; x1 += k0 + 5u;
    return x0 ^ x1;  // partitionable 32-bit random_bits = out0 ^ out1
}

__device__ __forceinline__ float gumbel_from_bits(uint32_t bits) {
    const float TINY = 1.17549435e-38f;
    float f = __uint_as_float((bits >> 9) | 0x3f800000u) - 1.0f;  // [0,1)
    float u = f * (1.0f - TINY) + TINY;
    u = fmaxf(TINY, u);
    return -logf(-logf(u));
}

// ---------------- fused scores + masked log-softmax + sample ----------------
__global__ void k_attn(const float* __restrict__ vt, int l,
                       uint32_t key0, uint32_t key1,
                       float* __restrict__ probs, float* __restrict__ tour) {
    int b = blockIdx.x, tid = threadIdx.x;  // 256 threads
    __shared__ float sb[Wn], sv[Wn], ssc[64];
    sb[tid] = g_blend2[b * Wn + tid];
    sv[tid] = vt[tid];
    __syncthreads();
    int warp = tid >> 5, lane = tid & 31;
    for (int s = warp; s < Sn; s += 8) {
        const float* row = g_blend1 + ((size_t)b * Sn + s) * Wn;
        float acc = 0.0f;
#pragma unroll
        for (int q = 0; q < 8; q++) {
            int w = lane + q * 32;
            acc += tanhf(row[w] + sb[w]) * sv[w];
        }
        for (int off = 16; off; off >>= 1) acc += __shfl_xor_sync(0xffffffffu, acc, off);
        if (lane == 0) ssc[s] = acc;
    }
    __syncthreads();
    if (warp != 0) return;
    int s0 = lane, s1 = lane + 32;
    const float NEG = -3.4e38f;
    float x0 = g_mask[b * Sn + s0] ? -100000.0f : ssc[s0];
    float x1 = NEG;
    if (s1 < Sn) x1 = g_mask[b * Sn + s1] ? -100000.0f : ssc[s1];
    float m = fmaxf(x0, x1);
    for (int off = 16; off; off >>= 1) m = fmaxf(m, __shfl_xor_sync(0xffffffffu, m, off));
    float sum = expf(x0 - m) + ((s1 < Sn) ? expf(x1 - m) : 0.0f);
    for (int off = 16; off; off >>= 1) sum += __shfl_xor_sync(0xffffffffu, sum, off);
    float lse = logf(sum);
    float lp0 = x0 - m - lse;
    float lp1 = x1 - m - lse;
    float* prow = probs + ((size_t)b * Ln + l) * Sn;
    prow[s0] = lp0;
    if (s1 < Sn) prow[s1] = lp1;
    float v0 = lp0 + gumbel_from_bits(threefry_xor(key0, key1, 0u, (uint32_t)(b * Sn + s0)));
    float v1 = NEG;
    if (s1 < Sn) v1 = lp1 + gumbel_from_bits(threefry_xor(key0, key1, 0u, (uint32_t)(b * Sn + s1)));
    float bv; int bi;
    if (v1 > v0) { bv = v1; bi = s1; } else { bv = v0; bi = s0; }
    for (int off = 16; off; off >>= 1) {
        float ov = __shfl_xor_sync(0xffffffffu, bv, off);
        int   oi = __shfl_xor_sync(0xffffffffu, bi, off);
        if (ov > bv || (ov == bv && oi < bi)) { bv = ov; bi = oi; }
    }
    if (lane == 0) {
        tour[(size_t)b * Ln + l] = (float)bi;
        g_mask[b * Sn + bi] = 1;
    }
}

// ---------------- host threefry ----------------
static void tf_host(uint32_t k0, uint32_t k1, uint32_t x0, uint32_t x1,
                    uint32_t& o0, uint32_t& o1) {
    uint32_t ks2 = k0 ^ k1 ^ 0x1BD11BDAu;
    x0 += k0; x1 += k1;
    const int ra[4] = {13, 15, 26, 6}, rb[4] = {17, 29, 16, 24};
    auto rl = [](uint32_t v, int d) { return (v << d) | (v >> (32 - d)); };
    for (int i = 0; i < 4; i++) { x0 += x1; x1 = rl(x1, ra[i]); x1 ^= x0; }
    x0 += k1; x1 += ks2 + 1u;
    for (int i = 0; i < 4; i++) { x0 += x1; x1 = rl(x1, rb[i]); x1 ^= x0; }
    x0 += ks2; x1 += k0 + 2u;
    for (int i = 0; i < 4; i++) { x0 += x1; x1 = rl(x1, ra[i]); x1 ^= x0; }
    x0 += k0; x1 += k1 + 3u;
    for (int i = 0; i < 4; i++) { x0 += x1; x1 = rl(x1, rb[i]); x1 ^= x0; }
    x0 += k1; x1 += ks2 + 4u;
    for (int i = 0; i < 4; i++) { x0 += x1; x1 = rl(x1, ra[i]); x1 ^= x0; }
    x0 += ks2; x1 += k0 + 5u;
    o0 = x0; o1 = x1;
}

extern "C" void kernel_launch(void* const* d_in, const int* in_sizes, int n_in,
                              void* d_out, int out_size) {
    const int*   input = (const int*)d_in[0];
    const float* emb   = (const float*)d_in[1];
    const float* eWih  = (const float*)d_in[2];
    const float* eWhh  = (const float*)d_in[3];
    const float* ebih  = (const float*)d_in[4];
    const float* ebhh  = (const float*)d_in[5];
    // d_in[6] = dec_Wih (unused: decoder input is always zero)
    const float* dWhh  = (const float*)d_in[7];
    const float* dbih  = (const float*)d_in[8];
    const float* dbhh  = (const float*)d_in[9];
    const float* W1    = (const float*)d_in[10];
    const float* W2    = (const float*)d_in[11];
    const float* vt    = (const float*)d_in[12];

    float* out   = (float*)d_out;
    float* probs = out;                               // [B, L, S]
    float* tour  = out + (size_t)Bn * Ln * Sn;        // [B, L] as float

    float *p_hT0, *p_hT1, *p_cT, *p_encT, *p_b1, *p_b2;
    float *p_encW2T, *p_decW2T, *p_W1T, *p_bd2, *p_P;
    cudaGetSymbolAddress((void**)&p_hT0, g_hT0);
    cudaGetSymbolAddress((void**)&p_hT1, g_hT1);
    cudaGetSymbolAddress((void**)&p_cT, g_cT);
    cudaGetSymbolAddress((void**)&p_encT, g_encT);
    cudaGetSymbolAddress((void**)&p_b1, g_blend1);
    cudaGetSymbolAddress((void**)&p_b2, g_blend2);
    cudaGetSymbolAddress((void**)&p_encW2T, g_encW2T);
    cudaGetSymbolAddress((void**)&p_decW2T, g_decW2T);
    cudaGetSymbolAddress((void**)&p_W1T, g_W1T);
    cudaGetSymbolAddress((void**)&p_bd2, g_bias_dec2);
    cudaGetSymbolAddress((void**)&p_P, g_P);

    const int BHB = (Bn * Hn + 255) / 256;

    k_prep<<<(Hn * ND + 255) / 256, 256>>>(eWhh, dWhh, dbih, dbhh, W2, W1);
    k_prep_P<<<(Vn * Gn + 255) / 256, 256>>>(emb, eWih, ebih, ebhh);
    k_init<<<BHB, 256>>>();

    // -------- encoder: 50 fused GEMM+cell steps, K=512 --------
    for (int t = 0; t < Sn; t++) {
        float* hin  = (t & 1) ? p_hT1 : p_hT0;
        float* hout = (t & 1) ? p_hT0 : p_hT1;
        gemm_fused<1><<<dim3(Gn / 128, Bn / 128), 256>>>(
            hin, Bn, p_encW2T, Gn, nullptr, p_P, input + t,
            nullptr, 0, hout, p_cT, p_encT, t);
    }

    // -------- blend1 = enc_states @ W1^T : [B*S, W] --------
    gemm_fused<0><<<dim3(Wn / 128, BSn / 128), 256>>>(
        p_encT, BSn, p_W1T, Wn, nullptr, nullptr, nullptr,
        p_b1, Wn, nullptr, nullptr, nullptr, 0);

    // -------- decoder first cell (h_prev = 0) --------
    k_dec0<<<BHB, 256>>>();

    // step keys: keys[l] = threefry2x32((0,42), (0,l))
    uint32_t K0[Ln], K1[Ln];
    for (int l = 0; l < Ln; l++) tf_host(0u, 42u, 0u, (uint32_t)l, K0[l], K1[l]);

    for (int l = 0; l < Ln; l++) {
        float* hin  = (l & 1) ? p_hT1 : p_hT0;
        float* hout = (l & 1) ? p_hT0 : p_hT1;
        // [gates_{l+2} | blend2_l] = h @ [decWhh_int; W2]^T ; cell fused
        gemm_fused<2><<<dim3(ND / 128, Bn / 128), 256>>>(
            hin, Bn, p_decW2T, ND, p_bd2, nullptr, nullptr,
            p_b2, Wn, hout, p_cT, nullptr, 0);
        k_attn<<<Bn, 256>>>(vt, l, K0[l], K1[l], probs, tour);
    }
    (void)in_sizes; (void)n_in; (void)out_size;
}